// round 1
// baseline (speedup 1.0000x reference)
#include <cuda_runtime.h>
#include <cuda_bf16.h>
#include <cstdint>

// Problem constants (fixed for this dataset instance)
#define NUM_B 32
#define NUM_C 128
#define NSEG (NUM_B * NUM_C)          // 4096
#define CNT_SHIFT 40
#define SUM_MASK ((1ULL << CNT_SHIFT) - 1ULL)
#define FIX_SCALE 4194304.0f          // 2^22
#define INV_FIX_SCALE (1.0f / 4194304.0f)

#define ACC_BLOCKS 1024
#define ACC_THREADS 256

// Global scratch: packed (count << 40) | fixed_point_sum per segment.
__device__ unsigned long long g_bins[NSEG];

// ---------------------------------------------------------------------------
// Kernel 1: zero the global bins (must run every launch for graph replay)
// ---------------------------------------------------------------------------
__global__ void zero_bins_kernel() {
    int i = blockIdx.x * blockDim.x + threadIdx.x;
    if (i < NSEG) g_bins[i] = 0ULL;
}

// ---------------------------------------------------------------------------
// Kernel 2: accumulate. Each block handles a contiguous chunk. batch_index is
// sorted, so the block's active segment window is [b0*C, (b1+1)*C).
// ---------------------------------------------------------------------------
__global__ void __launch_bounds__(ACC_THREADS)
accum_kernel(const float* __restrict__ reco,
             const float* __restrict__ target,
             const int* __restrict__ clabel,
             const int* __restrict__ bindex,
             int n, int n4, int chunk4) {
    __shared__ unsigned long long bins[NSEG];

    // zero shared bins
    for (int i = threadIdx.x; i < NSEG; i += ACC_THREADS) bins[i] = 0ULL;
    __syncthreads();

    const int start4 = blockIdx.x * chunk4;
    const int end4 = min(start4 + chunk4, n4);
    if (start4 >= n4) return;  // whole block exits together (after its own sync)

    const float4* r4 = (const float4*)reco;
    const float4* t4 = (const float4*)target;
    const int4* c4 = (const int4*)clabel;
    const int4* b4 = (const int4*)bindex;

    for (int i = start4 + threadIdx.x; i < end4; i += ACC_THREADS) {
        float4 r = r4[i];
        float4 t = t4[i];
        int4 c = c4[i];
        int4 b = b4[i];

        float d0 = r.x - t.x, d1 = r.y - t.y, d2 = r.z - t.z, d3 = r.w - t.w;
        float s0 = d0 * d0, s1 = d1 * d1, s2 = d2 * d2, s3 = d3 * d3;

        unsigned long long p0 = (1ULL << CNT_SHIFT) + (unsigned long long)(s0 * FIX_SCALE + 0.5f);
        unsigned long long p1 = (1ULL << CNT_SHIFT) + (unsigned long long)(s1 * FIX_SCALE + 0.5f);
        unsigned long long p2 = (1ULL << CNT_SHIFT) + (unsigned long long)(s2 * FIX_SCALE + 0.5f);
        unsigned long long p3 = (1ULL << CNT_SHIFT) + (unsigned long long)(s3 * FIX_SCALE + 0.5f);

        atomicAdd(&bins[b.x * NUM_C + c.x], p0);
        atomicAdd(&bins[b.y * NUM_C + c.y], p1);
        atomicAdd(&bins[b.z * NUM_C + c.z], p2);
        atomicAdd(&bins[b.w * NUM_C + c.w], p3);
    }

    // scalar tail (only last chunk can see it)
    const bool last_chunk = (end4 == n4);
    if (last_chunk) {
        for (int i = n4 * 4 + threadIdx.x; i < n; i += ACC_THREADS) {
            float d = reco[i] - target[i];
            float sq = d * d;
            unsigned long long p =
                (1ULL << CNT_SHIFT) + (unsigned long long)(sq * FIX_SCALE + 0.5f);
            atomicAdd(&bins[bindex[i] * NUM_C + clabel[i]], p);
        }
    }
    __syncthreads();

    // Flush only the segment window this chunk can touch (batch_index sorted).
    const int e_first = start4 * 4;
    const int e_last = last_chunk ? (n - 1) : (end4 * 4 - 1);
    const int b_lo = bindex[e_first];
    const int b_hi = bindex[e_last];
    const int s_lo = b_lo * NUM_C;
    const int s_hi = (b_hi + 1) * NUM_C;
    for (int s = s_lo + threadIdx.x; s < s_hi; s += ACC_THREADS) {
        unsigned long long v = bins[s];
        if (v) atomicAdd(&g_bins[s], v);
    }
}

// ---------------------------------------------------------------------------
// Kernel 3: finalize. 32 warps, one per batch. Two-level mean.
// ---------------------------------------------------------------------------
__global__ void __launch_bounds__(1024) finalize_kernel(float* __restrict__ out) {
    const int tid = threadIdx.x;
    const int warp = tid >> 5;
    const int lane = tid & 31;

    __shared__ float s_msum[NUM_B];
    __shared__ int s_pcnt[NUM_B];

    // warp `warp` reduces batch `warp` over its 128 clusters
    float msum = 0.0f;
    int pcnt = 0;
    for (int j = lane; j < NUM_C; j += 32) {
        unsigned long long v = g_bins[warp * NUM_C + j];
        unsigned int cnt = (unsigned int)(v >> CNT_SHIFT);
        if (cnt) {
            float sum = (float)(v & SUM_MASK) * INV_FIX_SCALE;
            msum += sum / (float)cnt;
            pcnt += 1;
        }
    }
#pragma unroll
    for (int off = 16; off > 0; off >>= 1) {
        msum += __shfl_down_sync(0xFFFFFFFFu, msum, off);
        pcnt += __shfl_down_sync(0xFFFFFFFFu, pcnt, off);
    }
    if (lane == 0) {
        s_msum[warp] = msum;
        s_pcnt[warp] = pcnt;
    }
    __syncthreads();

    if (warp == 0) {
        float bl = 0.0f;
        float bp = 0.0f;
        if (lane < NUM_B) {
            int pc = s_pcnt[lane];
            if (pc > 0) {
                bl = s_msum[lane] / (float)pc;
                bp = 1.0f;
            }
        }
#pragma unroll
        for (int off = 16; off > 0; off >>= 1) {
            bl += __shfl_down_sync(0xFFFFFFFFu, bl, off);
            bp += __shfl_down_sync(0xFFFFFFFFu, bp, off);
        }
        if (lane == 0) out[0] = bl / bp;
    }
}

// ---------------------------------------------------------------------------
extern "C" void kernel_launch(void* const* d_in, const int* in_sizes, int n_in,
                              void* d_out, int out_size) {
    const float* reco = (const float*)d_in[0];
    const float* target = (const float*)d_in[1];
    const int* clabel = (const int*)d_in[2];
    const int* bindex = (const int*)d_in[3];
    float* out = (float*)d_out;

    const int n = in_sizes[0];
    const int n4 = n >> 2;
    const int chunk4 = (n4 + ACC_BLOCKS - 1) / ACC_BLOCKS;

    zero_bins_kernel<<<(NSEG + 255) / 256, 256>>>();
    accum_kernel<<<ACC_BLOCKS, ACC_THREADS>>>(reco, target, clabel, bindex, n, n4, chunk4);
    finalize_kernel<<<1, 1024>>>(out);
}